// round 3
// baseline (speedup 1.0000x reference)
#include <cuda_runtime.h>
#include <math.h>

#define NGP_L 16
#define NGP_T (1 << 19)
#define N_PTS (64 * 64 * 64)
#define BLOCK 256

struct LevelParams {
    int res[NGP_L];
    unsigned dense_mask;
};

__global__ __launch_bounds__(BLOCK, 3)
void hashgrid_mlp_kernel(const float* __restrict__ points,
                         const float* __restrict__ table,
                         const float* __restrict__ w1,
                         const float* __restrict__ w2,
                         float* __restrict__ out,
                         LevelParams lp)
{
    __shared__ float sw1[64 * 32];
    __shared__ float sw2[64];
    __shared__ float senc[32 * BLOCK];   // enc staging: [feature][thread]

    const int tid = threadIdx.x;
    for (int i = tid; i < 64 * 32; i += BLOCK) sw1[i] = w1[i];
    if (tid < 64) sw2[tid] = w2[tid];
    __syncthreads();

    const int p = blockIdx.x * BLOCK + tid;   // N_PTS % BLOCK == 0

    const float px = points[3 * p + 0];
    const float py = points[3 * p + 1];
    const float pz = points[3 * p + 2];

    const unsigned M = (unsigned)(NGP_T - 1);

    // Process levels in pairs: compute indices for both, issue ALL loads
    // (wide + predicated fallback), then blend. Keeps ~12 independent load
    // events in flight per warp per burst.
#pragma unroll
    for (int lb = 0; lb < NGP_L; lb += 2) {
        unsigned idx0[2][4], idx1[2][4];
        float    fxs[2], wq[2][4];

#pragma unroll
        for (int s = 0; s < 2; s++) {
            const int   l     = lb + s;
            const int   res   = lp.res[l];
            const float rf    = (float)res;
            const bool  dense = (lp.dense_mask >> l) & 1u;
            const unsigned r1 = (unsigned)(res + 1);

            const float x = px * rf, y = py * rf, z = pz * rf;
            const float x0 = floorf(x), y0 = floorf(y), z0 = floorf(z);
            const float fx = x - x0, fy = y - y0, fz = z - z0;
            const unsigned cx0 = (unsigned)x0, cy0 = (unsigned)y0, cz0 = (unsigned)z0;

            if (dense) {
                const unsigned b  = cx0 + r1 * (cy0 + r1 * cz0);
                const unsigned dy = r1;
                const unsigned dz = r1 * r1;
                idx0[s][0] = b;           idx0[s][1] = b + dz;
                idx0[s][2] = b + dy;      idx0[s][3] = b + dy + dz;
#pragma unroll
                for (int q = 0; q < 4; q++) idx1[s][q] = idx0[s][q] + 1;
            } else {
                const unsigned ha = cy0 * 2654435761u, hb = ha + 2654435761u;
                const unsigned hc = cz0 * 805459861u,  hd = hc + 805459861u;
                const unsigned h0 = ha ^ hc, h1 = ha ^ hd, h2 = hb ^ hc, h3 = hb ^ hd;
                idx0[s][0] = (cx0 ^ h0) & M;  idx1[s][0] = ((cx0 + 1u) ^ h0) & M;
                idx0[s][1] = (cx0 ^ h1) & M;  idx1[s][1] = ((cx0 + 1u) ^ h1) & M;
                idx0[s][2] = (cx0 ^ h2) & M;  idx1[s][2] = ((cx0 + 1u) ^ h2) & M;
                idx0[s][3] = (cx0 ^ h3) & M;  idx1[s][3] = ((cx0 + 1u) ^ h3) & M;
            }

            fxs[s] = fx;
            const float wy0 = 1.0f - fy, wz0 = 1.0f - fz;
            wq[s][0] = wy0 * wz0;  wq[s][1] = wy0 * fz;
            wq[s][2] = fy  * wz0;  wq[s][3] = fy  * fz;
        }

        // Issue all wide loads for both levels first
        float4 v[2][4];
#pragma unroll
        for (int s = 0; s < 2; s++) {
            const float2* __restrict__ tab = (const float2*)table + (size_t)(lb + s) * NGP_T;
#pragma unroll
            for (int q = 0; q < 4; q++)
                v[s][q] = __ldg((const float4*)(tab + (idx0[s][q] & ~1u)));
        }

        // Then all predicated fallback loads (corner1 not adjacent to corner0)
        float2 fb[2][4];
#pragma unroll
        for (int s = 0; s < 2; s++) {
            const float2* __restrict__ tab = (const float2*)table + (size_t)(lb + s) * NGP_T;
#pragma unroll
            for (int q = 0; q < 4; q++) {
                fb[s][q] = make_float2(0.0f, 0.0f);
                if ((idx0[s][q] ^ idx1[s][q]) != 1u)
                    fb[s][q] = __ldg(tab + idx1[s][q]);
            }
        }

        // Blend both levels
#pragma unroll
        for (int s = 0; s < 2; s++) {
            const float fx = fxs[s];
            float e0 = 0.0f, e1 = 0.0f;
#pragma unroll
            for (int q = 0; q < 4; q++) {
                const bool odd0 = (idx0[s][q] & 1u);
                const bool adj  = ((idx0[s][q] ^ idx1[s][q]) == 1u);
                float2 c0 = odd0 ? make_float2(v[s][q].z, v[s][q].w)
                                 : make_float2(v[s][q].x, v[s][q].y);
                float2 c1 = adj ? (odd0 ? make_float2(v[s][q].x, v[s][q].y)
                                        : make_float2(v[s][q].z, v[s][q].w))
                                : fb[s][q];
                const float gx = fmaf(fx, c1.x - c0.x, c0.x);
                const float gy = fmaf(fx, c1.y - c0.y, c0.y);
                e0 = fmaf(wq[s][q], gx, e0);
                e1 = fmaf(wq[s][q], gy, e1);
            }
            senc[(2 * (lb + s) + 0) * BLOCK + tid] = e0;
            senc[(2 * (lb + s) + 1) * BLOCK + tid] = e1;
        }
    }

    // Pull enc back into registers (gather scratch is dead now)
    float enc[32];
#pragma unroll
    for (int k = 0; k < 32; k++) enc[k] = senc[k * BLOCK + tid];

    // Fused MLP: h = relu(enc @ w1^T) [64], out = sigmoid(h @ w2^T)
    float acc = 0.0f;
#pragma unroll 4
    for (int j = 0; j < 64; j++) {
        float h = 0.0f;
        const float* wr = &sw1[j * 32];
#pragma unroll
        for (int k = 0; k < 32; k++) h = fmaf(enc[k], wr[k], h);
        acc = fmaf(sw2[j], fmaxf(h, 0.0f), acc);
    }

    out[p] = 1.0f / (1.0f + __expf(-acc));
}

extern "C" void kernel_launch(void* const* d_in, const int* in_sizes, int n_in,
                              void* d_out, int out_size)
{
    const float* points = (const float*)d_in[0];   // [N_PTS, 3]
    const float* table  = (const float*)d_in[1];   // [L, T, 2]
    const float* w1     = (const float*)d_in[2];   // [64, 32]
    const float* w2     = (const float*)d_in[3];   // [1, 64]
    float* out = (float*)d_out;                    // [N_PTS]

    LevelParams lp;
    unsigned mask = 0;
    for (int l = 0; l < NGP_L; l++) {
        double r = floor(16.0 * pow(1.447269237440378, (double)l) + 1e-6);
        int res = (int)r;
        lp.res[l] = res;
        long long r1 = (long long)res + 1;
        if (r1 * r1 * r1 <= (long long)NGP_T) mask |= (1u << l);
    }
    lp.dense_mask = mask;

    hashgrid_mlp_kernel<<<N_PTS / BLOCK, BLOCK>>>(points, table, w1, w2, out, lp);
}